// round 5
// baseline (speedup 1.0000x reference)
#include <cuda_runtime.h>
#include <math.h>

#define APAD 68            // padded row stride (floats) for activation matrix A^T[256][APAD]
#define EPSV 1e-6f

__device__ float g_latconst[256];   // b1 + latent @ W1[25:153]  (constant across batch)

// ---------------------------------------------------------------------------
// Precompute: lat_const[n] = b1[n] + sum_j emb[traj,j] * W1[25+j, n]
// ---------------------------------------------------------------------------
__global__ void latconst_kernel(const float* __restrict__ emb,
                                const int* __restrict__ traj,
                                const float* __restrict__ W1,
                                const float* __restrict__ b1) {
    int n = threadIdx.x;
    int tid = traj[0];
    const float* e = emb + (size_t)tid * 128;
    float s = b1[n];
#pragma unroll 4
    for (int j = 0; j < 128; ++j)
        s = fmaf(e[j], W1[(size_t)(25 + j) * 256 + n], s);
    g_latconst[n] = s;
}

__device__ __forceinline__ float gelu_f(float x) {
    // exact (erf) GELU, matches jax.nn.gelu(approximate=False)
    return 0.5f * x * (1.0f + erff(x * 0.7071067811865476f));
}

// ---------------------------------------------------------------------------
// One dense layer: out[64 x 256] = A[64 x K] @ W[K x 256] + binit ; optional GELU.
// A stored transposed in smem: A[k][m], row stride APAD.
// Thread t owns rows m0..m0+3 (m0 = (t>>4)*4) and cols n = (t&15) + 16*j.
// ---------------------------------------------------------------------------
__device__ __noinline__ void dense_layer(float* __restrict__ A,
                                         float* __restrict__ Wc,
                                         const float* __restrict__ Wg,
                                         const float* __restrict__ binit,
                                         int K, int t, bool act) {
    const int nblk = t & 15;
    const int mblk = t >> 4;
    float acc[4][16];
#pragma unroll
    for (int j = 0; j < 16; ++j) {
        float b = binit[nblk + 16 * j];
        acc[0][j] = b; acc[1][j] = b; acc[2][j] = b; acc[3][j] = b;
    }

    for (int kc = 0; kc < K; kc += 16) {
        int kk = min(16, K - kc);
        int nflt = kk * 256;
        // stage weight chunk (flat, contiguous in global) via float4
        for (int idx = t * 4; idx < nflt; idx += 1024)
            *(float4*)(Wc + idx) = *(const float4*)(Wg + (size_t)kc * 256 + idx);
        __syncthreads();

        if (kk == 16) {
#pragma unroll
            for (int k2 = 0; k2 < 16; ++k2) {
                float4 a = *(const float4*)(A + (kc + k2) * APAD + mblk * 4);
                const float* wr = Wc + k2 * 256 + nblk;
#pragma unroll
                for (int j = 0; j < 16; ++j) {
                    float w = wr[16 * j];
                    acc[0][j] = fmaf(a.x, w, acc[0][j]);
                    acc[1][j] = fmaf(a.y, w, acc[1][j]);
                    acc[2][j] = fmaf(a.z, w, acc[2][j]);
                    acc[3][j] = fmaf(a.w, w, acc[3][j]);
                }
            }
        } else {
            for (int k2 = 0; k2 < kk; ++k2) {
                float4 a = *(const float4*)(A + (kc + k2) * APAD + mblk * 4);
                const float* wr = Wc + k2 * 256 + nblk;
#pragma unroll
                for (int j = 0; j < 16; ++j) {
                    float w = wr[16 * j];
                    acc[0][j] = fmaf(a.x, w, acc[0][j]);
                    acc[1][j] = fmaf(a.y, w, acc[1][j]);
                    acc[2][j] = fmaf(a.z, w, acc[2][j]);
                    acc[3][j] = fmaf(a.w, w, acc[3][j]);
                }
            }
        }
        __syncthreads();   // all reads of A (and Wc) for this chunk done
    }

    // write outputs back into A (in place; safe after the trailing sync above)
#pragma unroll
    for (int j = 0; j < 16; ++j) {
        int n = nblk + 16 * j;
        float4 v;
        v.x = act ? gelu_f(acc[0][j]) : acc[0][j];
        v.y = act ? gelu_f(acc[1][j]) : acc[1][j];
        v.z = act ? gelu_f(acc[2][j]) : acc[2][j];
        v.w = act ? gelu_f(acc[3][j]) : acc[3][j];
        *(float4*)(A + n * APAD + mblk * 4) = v;
    }
    __syncthreads();
}

// ---------------------------------------------------------------------------
// Main kernel: 64 particles per CTA, 256 threads.
// ---------------------------------------------------------------------------
__global__ void __launch_bounds__(256, 2)
stress_kernel(const float* __restrict__ Fg, const float* __restrict__ Cg,
              const float* __restrict__ W1,
              const float* __restrict__ W2, const float* __restrict__ b2,
              const float* __restrict__ W3, const float* __restrict__ b3,
              const float* __restrict__ W4, const float* __restrict__ b4,
              const float* __restrict__ W5, const float* __restrict__ b5,
              float* __restrict__ outg, int B) {
    extern __shared__ float smem[];
    float* A  = smem;                 // 256 * APAD floats
    float* Wc = A + 256 * APAD;       // 16 * 256 floats (also stages W5: 2304 floats)
    float* Rb = Wc + 16 * 256;        // 64 * 9 floats (polar rotations)

    const int t = threadIdx.x;
    const int g0 = blockIdx.x * 64;

    // ---- Phase 1: per-particle features (threads 0..63, one particle each) ----
    if (t < 64) {
        int g = g0 + t;
        if (g < B) {
            const float* Fp = Fg + (size_t)g * 9;
            float F0 = Fp[0], F1 = Fp[1], F2 = Fp[2];
            float F3 = Fp[3], F4 = Fp[4], F5 = Fp[5];
            float F6 = Fp[6], F7 = Fp[7], F8 = Fp[8];

            const float* Cp = Cg + (size_t)g * 9;
#pragma unroll
            for (int i = 0; i < 9; ++i) A[(16 + i) * APAD + t] = Cp[i];

            // M = F^T F   (F row-major: F[k][i] = F(3k+i))
            float M00 = F0*F0 + F3*F3 + F6*F6;
            float M01 = F0*F1 + F3*F4 + F6*F7;
            float M02 = F0*F2 + F3*F5 + F6*F8;
            float M11 = F1*F1 + F4*F4 + F7*F7;
            float M12 = F1*F2 + F4*F5 + F7*F8;
            float M22 = F2*F2 + F5*F5 + F8*F8;

            float det = F0*(F4*F8 - F5*F7) - F1*(F3*F8 - F5*F6) + F2*(F3*F7 - F4*F6);

            // closed-form eigenvalues of symmetric M (sorted descending)
            float q  = (M00 + M11 + M22) * (1.0f / 3.0f);
            float p1 = M01*M01 + M02*M02 + M12*M12;
            float d0 = M00 - q, d1 = M11 - q, d2 = M22 - q;
            float p2 = d0*d0 + d1*d1 + d2*d2 + 2.0f*p1;
            float p  = sqrtf(p2 * (1.0f / 6.0f) + 1e-30f);
            float ip = 1.0f / p;
            float B00 = d0*ip, B01 = M01*ip, B02 = M02*ip;
            float B11 = d1*ip, B12 = M12*ip, B22 = d2*ip;
            float detB = B00*(B11*B22 - B12*B12)
                       - B01*(B01*B22 - B12*B02)
                       + B02*(B01*B12 - B11*B02);
            float r = fminf(1.0f, fmaxf(-1.0f, 0.5f * detB));
            float phi = acosf(r) * (1.0f / 3.0f);
            float e1 = q + 2.0f * p * cosf(phi);
            float e3 = q + 2.0f * p * cosf(phi + 2.0943951023931953f);
            float e2 = 3.0f * q - e1 - e3;
            float s0 = sqrtf(fmaxf(e1, 0.0f));
            float s1 = sqrtf(fmaxf(e2, 0.0f));
            float s2 = sqrtf(fmaxf(e3, 0.0f));

            A[0*APAD + t] = s0 - 1.0f;
            A[1*APAD + t] = s1 - 1.0f;
            A[2*APAD + t] = s2 - 1.0f;
            A[3*APAD + t]  = M00 - 1.0f;
            A[4*APAD + t]  = M01;
            A[5*APAD + t]  = M02;
            A[6*APAD + t]  = M01;
            A[7*APAD + t]  = M11 - 1.0f;
            A[8*APAD + t]  = M12;
            A[9*APAD + t]  = M02;
            A[10*APAD + t] = M12;
            A[11*APAD + t] = M22 - 1.0f;
            A[12*APAD + t] = det - 1.0f;
            A[13*APAD + t] = logf(det) - 1.0f;
            float f00 = fmaxf(F0, EPSV);
            A[14*APAD + t] = f00 - 1.0f;
            A[15*APAD + t] = logf(f00) - 1.0f;

            // polar rotation R via Newton iteration X <- 0.5 (X + X^-T)
            float X0=F0, X1=F1, X2=F2, X3=F3, X4=F4, X5=F5, X6=F6, X7=F7, X8=F8;
#pragma unroll
            for (int it = 0; it < 4; ++it) {
                float C00 =   X4*X8 - X5*X7;
                float C01 = -(X3*X8 - X5*X6);
                float C02 =   X3*X7 - X4*X6;
                float C10 = -(X1*X8 - X2*X7);
                float C11 =   X0*X8 - X2*X6;
                float C12 = -(X0*X7 - X1*X6);
                float C20 =   X1*X5 - X2*X4;
                float C21 = -(X0*X5 - X2*X3);
                float C22 =   X0*X4 - X1*X3;
                float dX  = X0*C00 + X1*C01 + X2*C02;
                float h   = 0.5f / dX;     // cofactor/det = X^-T
                X0 = 0.5f*X0 + C00*h; X1 = 0.5f*X1 + C01*h; X2 = 0.5f*X2 + C02*h;
                X3 = 0.5f*X3 + C10*h; X4 = 0.5f*X4 + C11*h; X5 = 0.5f*X5 + C12*h;
                X6 = 0.5f*X6 + C20*h; X7 = 0.5f*X7 + C21*h; X8 = 0.5f*X8 + C22*h;
            }
            Rb[t*9+0]=X0; Rb[t*9+1]=X1; Rb[t*9+2]=X2;
            Rb[t*9+3]=X3; Rb[t*9+4]=X4; Rb[t*9+5]=X5;
            Rb[t*9+6]=X6; Rb[t*9+7]=X7; Rb[t*9+8]=X8;
        } else {
            for (int k = 0; k < 25; ++k) A[k*APAD + t] = 0.0f;
        }
    }
    __syncthreads();

    // ---- Phase 2: MLP ----
    dense_layer(A, Wc, W1, g_latconst, 25, t, true);   // layer 1 (latent folded into bias)
    {
        const float* Ws[3] = {W2, W3, W4};
        const float* bs[3] = {b2, b3, b4};
#pragma unroll 1
        for (int L = 0; L < 3; ++L)
            dense_layer(A, Wc, Ws[L], bs[L], 256, t, true);
    }

    // ---- Layer 5 (256 -> 9) + epilogue ----
    for (int idx = t; idx < 576; idx += 256)            // stage W5 (2304 floats)
        ((float4*)Wc)[idx] = ((const float4*)W5)[idx];
    __syncthreads();

    if (t < 64) {
        int g = g0 + t;
        if (g < B) {
            float o[9];
#pragma unroll
            for (int j = 0; j < 9; ++j) o[j] = b5[j];
#pragma unroll 4
            for (int k = 0; k < 256; ++k) {
                float a = A[k*APAD + t];
                const float* wr = Wc + k * 9;
#pragma unroll
                for (int j = 0; j < 9; ++j) o[j] = fmaf(a, wr[j], o[j]);
            }
            // symmetrize
            float x00 = o[0], x11 = o[4], x22 = o[8];
            float x01 = 0.5f * (o[1] + o[3]);
            float x02 = 0.5f * (o[2] + o[6]);
            float x12 = 0.5f * (o[5] + o[7]);

            float R0=Rb[t*9+0], R1=Rb[t*9+1], R2=Rb[t*9+2];
            float R3=Rb[t*9+3], R4=Rb[t*9+4], R5=Rb[t*9+5];
            float R6=Rb[t*9+6], R7=Rb[t*9+7], R8=Rb[t*9+8];

            // P = R @ sym(x)
            float P00 = R0*x00 + R1*x01 + R2*x02;
            float P01 = R0*x01 + R1*x11 + R2*x12;
            float P02 = R0*x02 + R1*x12 + R2*x22;
            float P10 = R3*x00 + R4*x01 + R5*x02;
            float P11 = R3*x01 + R4*x11 + R5*x12;
            float P12 = R3*x02 + R4*x12 + R5*x22;
            float P20 = R6*x00 + R7*x01 + R8*x02;
            float P21 = R6*x01 + R7*x11 + R8*x12;
            float P22 = R6*x02 + R7*x12 + R8*x22;

            const float* Fp = Fg + (size_t)g * 9;
            float F0 = Fp[0], F1 = Fp[1], F2 = Fp[2];
            float F3 = Fp[3], F4 = Fp[4], F5 = Fp[5];
            float F6 = Fp[6], F7 = Fp[7], F8 = Fp[8];

            // cauchy = P @ F^T  :  c[i][j] = sum_k P[i][k] * F[j][k]
            float* op = outg + (size_t)g * 9;
            op[0] = P00*F0 + P01*F1 + P02*F2;
            op[1] = P00*F3 + P01*F4 + P02*F5;
            op[2] = P00*F6 + P01*F7 + P02*F8;
            op[3] = P10*F0 + P11*F1 + P12*F2;
            op[4] = P10*F3 + P11*F4 + P12*F5;
            op[5] = P10*F6 + P11*F7 + P12*F8;
            op[6] = P20*F0 + P21*F1 + P22*F2;
            op[7] = P20*F3 + P21*F4 + P22*F5;
            op[8] = P20*F6 + P21*F7 + P22*F8;
        }
    }
}

// ---------------------------------------------------------------------------
extern "C" void kernel_launch(void* const* d_in, const int* in_sizes, int n_in,
                              void* d_out, int out_size) {
    const float* F    = (const float*)d_in[0];
    const float* C    = (const float*)d_in[1];
    const float* emb  = (const float*)d_in[2];
    const int*   traj = (const int*)d_in[3];
    const float* W1 = (const float*)d_in[4];
    const float* b1 = (const float*)d_in[5];
    const float* W2 = (const float*)d_in[6];
    const float* b2 = (const float*)d_in[7];
    const float* W3 = (const float*)d_in[8];
    const float* b3 = (const float*)d_in[9];
    const float* W4 = (const float*)d_in[10];
    const float* b4 = (const float*)d_in[11];
    const float* W5 = (const float*)d_in[12];
    const float* b5 = (const float*)d_in[13];

    int B = in_sizes[0] / 9;

    latconst_kernel<<<1, 256>>>(emb, traj, W1, b1);

    size_t smem = (size_t)(256 * APAD + 16 * 256 + 64 * 9) * sizeof(float);
    cudaFuncSetAttribute(stress_kernel, cudaFuncAttributeMaxDynamicSharedMemorySize, (int)smem);

    int grid = (B + 63) / 64;
    stress_kernel<<<grid, 256, smem>>>(F, C, W1, W2, b2, W3, b3, W4, b4, W5, b5,
                                       (float*)d_out, B);
}

// round 11
// speedup vs baseline: 1.8172x; 1.8172x over previous
#include <cuda_runtime.h>
#include <cuda_fp16.h>
#include <math.h>
#include <stdint.h>

#define EPSV 1e-6f

// ---- smem byte layout (203,264 B total) ----
#define SA0H 0        // A buf0 hi: [64m][256k] fp16, 512B rows, XOR (m&7)<<4
#define SA0L 32768    // A buf0 lo
#define SA1H 65536    // A buf1 hi
#define SA1L 98304    // A buf1 lo
#define SW0  131072   // W slot 0: 32KB = hi 16KB + lo 16KB (k32 chunk, 64B rows)
#define SW1  163840   // W slot 1
#define SB0  196608   // bias slot 0 (256 f32)
#define SB1  197632   // bias slot 1
#define SD   198656   // L5 staging D[64][18] f32 (4608 B)
#define SM_TOTAL 203264

// ---- device scratch: pre-split, pre-swizzled fp16 weight images ----
__device__ __align__(16) unsigned char g_W1img[32768];    // [256n][32k] hi 16K + lo 16K
__device__ __align__(16) unsigned char g_W234img[786432]; // 3 layers x 8 chunks x (hi16K+lo16K)
__device__ __align__(16) unsigned char g_W5img[16384];    // [16n][256k] hi 8K + lo 8K (512B rows)
__device__ __align__(16) float g_latconst[256];

static __device__ __forceinline__ uint32_t smem_u32(const void* p){
    uint32_t a; asm("{ .reg .u64 t; cvta.to.shared.u64 t, %1; cvt.u32.u64 %0, t; }":"=r"(a):"l"(p)); return a;
}
static __device__ __forceinline__ void cp16(uint32_t d, const void* s){
    asm volatile("cp.async.cg.shared.global [%0], [%1], 16;"::"r"(d),"l"(s));
}
#define CP_COMMIT() asm volatile("cp.async.commit_group;":::"memory")
#define CP_WAIT0()  asm volatile("cp.async.wait_group 0;":::"memory")
#define CP_WAIT1()  asm volatile("cp.async.wait_group 1;":::"memory")

static __device__ __forceinline__ void mma16816(float* c, uint32_t a0, uint32_t a1, uint32_t a2, uint32_t a3,
                                                uint32_t b0, uint32_t b1){
    asm volatile("mma.sync.aligned.m16n8k16.row.col.f32.f16.f16.f32 "
                 "{%0,%1,%2,%3},{%4,%5,%6,%7},{%8,%9},{%0,%1,%2,%3};"
                 : "+f"(c[0]),"+f"(c[1]),"+f"(c[2]),"+f"(c[3])
                 : "r"(a0),"r"(a1),"r"(a2),"r"(a3),"r"(b0),"r"(b1));
}
static __device__ __forceinline__ float gelu_fast(float x){
    float z = fabsf(x)*0.70710678118654752f;
    float tt = __fdividef(1.0f, fmaf(0.3275911f, z, 1.0f));
    float poly = fmaf(fmaf(fmaf(fmaf(1.061405429f,tt,-1.453152027f),tt,1.421413741f),tt,-0.284496736f),tt,0.254829592f)*tt;
    float e = fmaf(-poly, __expf(-z*z), 1.0f);
    return 0.5f*x*(1.0f + copysignf(e, x));
}
// split x into hi+lo fp16 pair, packed as two half2 words for columns (a,b)
static __device__ __forceinline__ void pack_split(float a, float b, uint32_t &ph, uint32_t &pl){
    __half ha = __float2half_rn(a), hb = __float2half_rn(b);
    __half la = __float2half_rn(a - __half2float(ha));
    __half lb = __float2half_rn(b - __half2float(hb));
    __half2 H = __halves2half2(ha,hb), L = __halves2half2(la,lb);
    ph = *(uint32_t*)&H; pl = *(uint32_t*)&L;
}

// ---------------- prep kernels ----------------
__global__ void latconst_kernel(const float* __restrict__ emb, const int* __restrict__ traj,
                                const float* __restrict__ W1, const float* __restrict__ b1){
    int n = threadIdx.x;
    const float* e = emb + (size_t)traj[0]*128;
    float s = b1[n];
#pragma unroll 4
    for (int j = 0; j < 128; ++j) s = fmaf(e[j], W1[(size_t)(25+j)*256+n], s);
    g_latconst[n] = s;
}

__global__ void prep_weights(const float* __restrict__ W1, const float* __restrict__ W2,
                             const float* __restrict__ W3, const float* __restrict__ W4,
                             const float* __restrict__ W5){
    int i = blockIdx.x*256 + threadIdx.x;            // 816 blocks x 256 = 208896
    float v; unsigned char* dst; uint32_t off; int lo_delta;
    if (i < 196608) {                                // W2/3/4: [n][k] -> k32 chunks, 64B rows
        int l = i / 65536, r = i % 65536, k = r >> 8, n = r & 255;
        const float* W = (l==0)?W2:(l==1)?W3:W4;
        v = W[(size_t)k*256+n];
        int c = k>>5, kl = k&31;
        off = (uint32_t)l*262144u + (uint32_t)c*32768u + (uint32_t)n*64u
            + (((uint32_t)kl*2u) ^ ((((uint32_t)n>>1)&3u)<<4));
        dst = g_W234img; lo_delta = 16384;
    } else if (i < 204800) {                         // W1: [256n][32k] pad k>=25, 64B rows
        int r = i-196608, n = r>>5, k = r&31;
        v = (k<25)? W1[(size_t)k*256+n] : 0.0f;
        off = (uint32_t)n*64u + (((uint32_t)k*2u) ^ ((((uint32_t)n>>1)&3u)<<4));
        dst = g_W1img; lo_delta = 16384;
    } else if (i < 208896) {                         // W5: [16n][256k] pad n>=9, 512B rows
        int r = i-204800, k = r>>4, n = r&15;
        v = (n<9)? W5[(size_t)k*9+n] : 0.0f;
        off = (uint32_t)n*512u + (((uint32_t)k*2u) ^ (((uint32_t)(n&7))<<4));
        dst = g_W5img; lo_delta = 8192;
    } else return;
    __half h = __float2half_rn(v);
    __half l = __float2half_rn(v - __half2float(h));
    *(__half*)(dst + off) = h;
    *(__half*)(dst + off + lo_delta) = l;
}

// ---------------- MMA building blocks ----------------
static __device__ __forceinline__ void issue_chunk(uint32_t smb, int slotOff,
                                                   const unsigned char* src, int bytes, int t){
    int n16 = bytes >> 4;
    for (int i = t; i < n16; i += 256) cp16(smb + slotOff + i*16, src + (size_t)i*16);
}

// one k16 step, 3 products (AhWh + AhWl + AlWh), all 2x8 tiles
template<int ASTR>
static __device__ __forceinline__ void step16_all(const char* sm, int aH, int m0g,
        int wslot, int wrowBase, int kbA, int kbW, uint32_t gxA, uint32_t gxW,
        float (&acc)[2][8][4]){
    uint32_t k0A = (uint32_t)kbA ^ gxA, k1A = (uint32_t)(kbA+16) ^ gxA;
    uint32_t k0W = (uint32_t)kbW ^ gxW, k1W = (uint32_t)(kbW+16) ^ gxW;
    uint32_t ah[2][4], al[2][4];
#pragma unroll
    for (int mt=0; mt<2; ++mt){
        const char* abh = sm + aH + (m0g + mt*16)*ASTR;
        const char* abl = abh + 32768;
        ah[mt][0]=*(const uint32_t*)(abh+k0A); ah[mt][1]=*(const uint32_t*)(abh+8*ASTR+k0A);
        ah[mt][2]=*(const uint32_t*)(abh+k1A); ah[mt][3]=*(const uint32_t*)(abh+8*ASTR+k1A);
        al[mt][0]=*(const uint32_t*)(abl+k0A); al[mt][1]=*(const uint32_t*)(abl+8*ASTR+k0A);
        al[mt][2]=*(const uint32_t*)(abl+k1A); al[mt][3]=*(const uint32_t*)(abl+8*ASTR+k1A);
    }
    uint32_t bh[8][2], bl[8][2];
#pragma unroll
    for (int nt=0; nt<8; ++nt){
        const char* wbh = sm + wslot + wrowBase + nt*512;
        const char* wbl = wbh + 16384;
        bh[nt][0]=*(const uint32_t*)(wbh+k0W); bh[nt][1]=*(const uint32_t*)(wbh+k1W);
        bl[nt][0]=*(const uint32_t*)(wbl+k0W); bl[nt][1]=*(const uint32_t*)(wbl+k1W);
    }
#pragma unroll
    for (int mt=0; mt<2; ++mt)
#pragma unroll
        for (int nt=0; nt<8; ++nt){
            mma16816(acc[mt][nt], ah[mt][0],ah[mt][1],ah[mt][2],ah[mt][3], bh[nt][0],bh[nt][1]);
            mma16816(acc[mt][nt], ah[mt][0],ah[mt][1],ah[mt][2],ah[mt][3], bl[nt][0],bl[nt][1]);
            mma16816(acc[mt][nt], al[mt][0],al[mt][1],al[mt][2],al[mt][3], bh[nt][0],bh[nt][1]);
        }
}

static __device__ __forceinline__ void epilogue(char* sm, int aoutH, int biasOff,
        int m0g, int wn, int tig, uint32_t gxOut, float (&acc)[2][8][4]){
#pragma unroll
    for (int mt=0; mt<2; ++mt){
        char* rbh = sm + aoutH + (m0g + mt*16)*512;
        char* rbl = rbh + 32768;
#pragma unroll
        for (int nt=0; nt<8; ++nt){
            int n0 = wn*64 + nt*8 + 2*tig;
            float2 bb = *(const float2*)(sm + biasOff + n0*4);
            float* c = acc[mt][nt];
            float y0 = gelu_fast(c[0]+bb.x), y1 = gelu_fast(c[1]+bb.y);
            float y2 = gelu_fast(c[2]+bb.x), y3 = gelu_fast(c[3]+bb.y);
            uint32_t kb = ((uint32_t)(n0*2)) ^ gxOut;
            uint32_t ph0,pl0,ph1,pl1;
            pack_split(y0,y1,ph0,pl0); pack_split(y2,y3,ph1,pl1);
            *(uint32_t*)(rbh + kb)        = ph0;
            *(uint32_t*)(rbh + 4096 + kb) = ph1;
            *(uint32_t*)(rbl + kb)        = pl0;
            *(uint32_t*)(rbl + 4096 + kb) = pl1;
        }
    }
}

static __device__ __forceinline__ void big_layer(char* sm, uint32_t smb, int t,
        int wm, int wn, int g, int tig,
        int ainH, int aoutH, int biasOff, const unsigned char* img,
        const unsigned char* nextimg, int nextbytes, const float* nextbias, int nbOff){
    float acc[2][8][4];
#pragma unroll
    for (int mt=0;mt<2;++mt)
#pragma unroll
        for (int nt=0;nt<8;++nt)
#pragma unroll
            for (int j=0;j<4;++j) acc[mt][nt][j]=0.0f;
    uint32_t gxA = (uint32_t)g<<4, gxW = (((uint32_t)g>>1)&3u)<<4;
    int m0g = wm*32 + g;
    int wrowBase = (wn*64 + g)*64;
#pragma unroll 1
    for (int u=0; u<8; ++u){
        int cur = (u&1)? SW0 : SW1;
        int nxt = (u&1)? SW1 : SW0;
        if (u<7) issue_chunk(smb, nxt, img + (size_t)(u+1)*32768u, 32768, t);
        else { issue_chunk(smb, nxt, nextimg, nextbytes, t);
               if (nextbias && t<64) cp16(smb + nbOff + t*16, (const char*)nextbias + t*16); }
        CP_COMMIT(); CP_WAIT1(); __syncthreads();
#pragma unroll
        for (int s=0;s<2;++s)
            step16_all<512>(sm, ainH, m0g, cur, wrowBase,
                            u*64 + s*32 + 4*tig, s*32 + 4*tig, gxA, gxW, acc);
        __syncthreads();
    }
    epilogue(sm, aoutH, biasOff, m0g, wn, tig, gxA, acc);
}

// ---------------- main kernel: 64 particles / CTA, 256 threads ----------------
__global__ void __launch_bounds__(256, 1)
mlp_kernel(const float* __restrict__ Fg, const float* __restrict__ Cg,
           const float* __restrict__ b2, const float* __restrict__ b3,
           const float* __restrict__ b4, const float* __restrict__ b5,
           float* __restrict__ outg, int B){
    extern __shared__ char sm[];
    const uint32_t smb = smem_u32(sm);
    const int t = threadIdx.x, w = t>>5, lane = t&31;
    const int g = lane>>2, tig = lane&3;
    const int wm = w>>2, wn = w&3;
    const int g0 = blockIdx.x*64;

    // group0: W1(hi+lo) -> SW0, latconst -> SB0 ; group1: L2 chunk0 -> SW1, b2 -> SB1
    issue_chunk(smb, SW0, g_W1img, 32768, t);
    if (t<64) cp16(smb + SB0 + t*16, (const char*)g_latconst + t*16);
    CP_COMMIT();
    issue_chunk(smb, SW1, g_W234img, 32768, t);
    if (t<64) cp16(smb + SB1 + t*16, (const char*)b2 + t*16);
    CP_COMMIT();

    // ---- phase 1: features (hi/lo, 64B rows) + polar rotation in regs ----
    float R0=0,R1=0,R2=0,R3=0,R4=0,R5=0,R6=0,R7=0,R8=0;
    float F0=0,F1=0,F2=0,F3=0,F4=0,F5=0,F6=0,F7=0,F8=0;
    if (t < 64){
        int gp = g0 + t;
        float feat[25];
#pragma unroll
        for (int i=0;i<25;++i) feat[i]=0.0f;
        if (gp < B){
            const float* Fp = Fg + (size_t)gp*9;
            F0=Fp[0];F1=Fp[1];F2=Fp[2];F3=Fp[3];F4=Fp[4];F5=Fp[5];F6=Fp[6];F7=Fp[7];F8=Fp[8];
            float M00=F0*F0+F3*F3+F6*F6, M01=F0*F1+F3*F4+F6*F7, M02=F0*F2+F3*F5+F6*F8;
            float M11=F1*F1+F4*F4+F7*F7, M12=F1*F2+F4*F5+F7*F8, M22=F2*F2+F5*F5+F8*F8;
            float det = F0*(F4*F8-F5*F7) - F1*(F3*F8-F5*F6) + F2*(F3*F7-F4*F6);
            float q=(M00+M11+M22)*(1.0f/3.0f);
            float p1=M01*M01+M02*M02+M12*M12;
            float d0=M00-q,d1=M11-q,d2=M22-q;
            float p=sqrtf((d0*d0+d1*d1+d2*d2+2.0f*p1)*(1.0f/6.0f)+1e-30f);
            float ip=1.0f/p;
            float B00=d0*ip,B01=M01*ip,B02=M02*ip,B11=d1*ip,B12=M12*ip,B22=d2*ip;
            float detB=B00*(B11*B22-B12*B12)-B01*(B01*B22-B12*B02)+B02*(B01*B12-B11*B02);
            float rr=fminf(1.0f,fmaxf(-1.0f,0.5f*detB));
            float phi=acosf(rr)*(1.0f/3.0f);
            float e1=q+2.0f*p*cosf(phi);
            float e3=q+2.0f*p*cosf(phi+2.0943951023931953f);
            float e2=3.0f*q-e1-e3;
            float f00=fmaxf(F0,EPSV);
            feat[0]=sqrtf(fmaxf(e1,0.0f))-1.0f; feat[1]=sqrtf(fmaxf(e2,0.0f))-1.0f; feat[2]=sqrtf(fmaxf(e3,0.0f))-1.0f;
            feat[3]=M00-1.0f; feat[4]=M01; feat[5]=M02; feat[6]=M01; feat[7]=M11-1.0f; feat[8]=M12;
            feat[9]=M02; feat[10]=M12; feat[11]=M22-1.0f;
            feat[12]=det-1.0f; feat[13]=logf(det)-1.0f; feat[14]=f00-1.0f; feat[15]=logf(f00)-1.0f;
            const float* Cp = Cg + (size_t)gp*9;
#pragma unroll
            for (int i=0;i<9;++i) feat[16+i]=Cp[i];
            float X0=F0,X1=F1,X2=F2,X3=F3,X4=F4,X5=F5,X6=F6,X7=F7,X8=F8;
#pragma unroll
            for (int it=0; it<4; ++it){
                float C00=X4*X8-X5*X7, C01=-(X3*X8-X5*X6), C02=X3*X7-X4*X6;
                float C10=-(X1*X8-X2*X7), C11=X0*X8-X2*X6, C12=-(X0*X7-X1*X6);
                float C20=X1*X5-X2*X4, C21=-(X0*X5-X2*X3), C22=X0*X4-X1*X3;
                float h = 0.5f/(X0*C00+X1*C01+X2*C02);
                X0=0.5f*X0+C00*h; X1=0.5f*X1+C01*h; X2=0.5f*X2+C02*h;
                X3=0.5f*X3+C10*h; X4=0.5f*X4+C11*h; X5=0.5f*X5+C12*h;
                X6=0.5f*X6+C20*h; X7=0.5f*X7+C21*h; X8=0.5f*X8+C22*h;
            }
            R0=X0;R1=X1;R2=X2;R3=X3;R4=X4;R5=X5;R6=X6;R7=X7;R8=X8;
        }
        uint32_t fxt = (((uint32_t)t>>1)&3u)<<4;
        char* frh = sm + SA0H + t*64;
        char* frl = sm + SA0L + t*64;
#pragma unroll
        for (int j=0;j<16;++j){
            float x0 = (2*j   < 25)? feat[2*j]   : 0.0f;
            float x1 = (2*j+1 < 25)? feat[2*j+1] : 0.0f;
            uint32_t ph,pl; pack_split(x0,x1,ph,pl);
            *(uint32_t*)(frh + (((uint32_t)(4*j)) ^ fxt)) = ph;
            *(uint32_t*)(frl + (((uint32_t)(4*j)) ^ fxt)) = pl;
        }
    }

    // ---- L1: features (k32) x W1 -> SA1 ----
    CP_WAIT1();
    __syncthreads();
    {
        float acc[2][8][4];
#pragma unroll
        for (int mt=0;mt<2;++mt)
#pragma unroll
            for (int nt=0;nt<8;++nt)
#pragma unroll
                for (int j=0;j<4;++j) acc[mt][nt][j]=0.0f;
        uint32_t gxW = (((uint32_t)g>>1)&3u)<<4;
        int m0g = wm*32 + g;
        int wrowBase = (wn*64 + g)*64;
#pragma unroll
        for (int s=0;s<2;++s)
            step16_all<64>(sm, SA0H, m0g, SW0, wrowBase, s*32+4*tig, s*32+4*tig, gxW, gxW, acc);
        __syncthreads();                    // all warps done with SW0 + features
        epilogue(sm, SA1H, SB0, m0g, wn, tig, (uint32_t)g<<4, acc);
    }

    // ---- L2, L3, L4 ----
    big_layer(sm, smb, t, wm, wn, g, tig, SA1H, SA0H, SB1,
              g_W234img,          g_W234img + 262144, 32768, b3, SB0);
    big_layer(sm, smb, t, wm, wn, g, tig, SA0H, SA1H, SB0,
              g_W234img + 262144, g_W234img + 524288, 32768, b4, SB1);
    big_layer(sm, smb, t, wm, wn, g, tig, SA1H, SA0H, SB1,
              g_W234img + 524288, g_W5img, 16384, (const float*)0, 0);

    // ---- L5: SA0 x W5 (SW1) -> D[64][16] ----
    CP_WAIT0();
    __syncthreads();
    if (w < 4){
        float acc5[2][4];
#pragma unroll
        for (int nt=0;nt<2;++nt)
#pragma unroll
            for (int j=0;j<4;++j) acc5[nt][j]=0.0f;
        int m0 = w*16 + g;
        const char* abh = sm + SA0H + m0*512;
        const char* abl = abh + 32768;
        uint32_t gx = (uint32_t)g<<4;
#pragma unroll
        for (int kc=0; kc<16; ++kc){
            int kb = kc*32 + 4*tig;
            uint32_t k0 = (uint32_t)kb ^ gx, k1 = (uint32_t)(kb+16) ^ gx;
            uint32_t ah0=*(const uint32_t*)(abh+k0), ah1=*(const uint32_t*)(abh+4096+k0);
            uint32_t ah2=*(const uint32_t*)(abh+k1), ah3=*(const uint32_t*)(abh+4096+k1);
            uint32_t al0=*(const uint32_t*)(abl+k0), al1=*(const uint32_t*)(abl+4096+k0);
            uint32_t al2=*(const uint32_t*)(abl+k1), al3=*(const uint32_t*)(abl+4096+k1);
#pragma unroll
            for (int nt=0; nt<2; ++nt){
                const char* wbh = sm + SW1 + (nt*8+g)*512;
                const char* wbl = wbh + 8192;
                uint32_t bh0=*(const uint32_t*)(wbh+k0), bh1=*(const uint32_t*)(wbh+k1);
                uint32_t bl0=*(const uint32_t*)(wbl+k0), bl1=*(const uint32_t*)(wbl+k1);
                mma16816(acc5[nt], ah0,ah1,ah2,ah3, bh0,bh1);
                mma16816(acc5[nt], ah0,ah1,ah2,ah3, bl0,bl1);
                mma16816(acc5[nt], al0,al1,al2,al3, bh0,bh1);
            }
        }
#pragma unroll
        for (int nt=0; nt<2; ++nt){
            int n0 = nt*8 + 2*tig;
            *(float2*)(sm + SD + ((size_t)m0*18 + n0)*4)     = make_float2(acc5[nt][0], acc5[nt][1]);
            *(float2*)(sm + SD + ((size_t)(m0+8)*18 + n0)*4) = make_float2(acc5[nt][2], acc5[nt][3]);
        }
    }
    __syncthreads();

    // ---- final epilogue: symmetrize, P = R x, cauchy = P F^T ----
    if (t < 64){
        int gp = g0 + t;
        if (gp < B){
            const float* dr = (const float*)(sm + SD + (size_t)t*72);
            float o[9];
#pragma unroll
            for (int j=0;j<9;++j) o[j] = dr[j] + b5[j];
            float x00=o[0], x11=o[4], x22=o[8];
            float x01=0.5f*(o[1]+o[3]), x02=0.5f*(o[2]+o[6]), x12=0.5f*(o[5]+o[7]);
            float P00=R0*x00+R1*x01+R2*x02, P01=R0*x01+R1*x11+R2*x12, P02=R0*x02+R1*x12+R2*x22;
            float P10=R3*x00+R4*x01+R5*x02, P11=R3*x01+R4*x11+R5*x12, P12=R3*x02+R4*x12+R5*x22;
            float P20=R6*x00+R7*x01+R8*x02, P21=R6*x01+R7*x11+R8*x12, P22=R6*x02+R7*x12+R8*x22;
            float* op = outg + (size_t)gp*9;
            op[0]=P00*F0+P01*F1+P02*F2; op[1]=P00*F3+P01*F4+P02*F5; op[2]=P00*F6+P01*F7+P02*F8;
            op[3]=P10*F0+P11*F1+P12*F2; op[4]=P10*F3+P11*F4+P12*F5; op[5]=P10*F6+P11*F7+P12*F8;
            op[6]=P20*F0+P21*F1+P22*F2; op[7]=P20*F3+P21*F4+P22*F5; op[8]=P20*F6+P21*F7+P22*F8;
        }
    }
}

// ---------------------------------------------------------------------------
extern "C" void kernel_launch(void* const* d_in, const int* in_sizes, int n_in,
                              void* d_out, int out_size){
    const float* F   = (const float*)d_in[0];
    const float* C   = (const float*)d_in[1];
    const float* emb = (const float*)d_in[2];
    const int* traj  = (const int*)d_in[3];
    const float* W1 = (const float*)d_in[4];  const float* b1 = (const float*)d_in[5];
    const float* W2 = (const float*)d_in[6];  const float* b2 = (const float*)d_in[7];
    const float* W3 = (const float*)d_in[8];  const float* b3 = (const float*)d_in[9];
    const float* W4 = (const float*)d_in[10]; const float* b4 = (const float*)d_in[11];
    const float* W5 = (const float*)d_in[12]; const float* b5 = (const float*)d_in[13];
    int B = in_sizes[0] / 9;

    latconst_kernel<<<1, 256>>>(emb, traj, W1, b1);
    prep_weights<<<816, 256>>>(W1, W2, W3, W4, W5);

    cudaFuncSetAttribute(mlp_kernel, cudaFuncAttributeMaxDynamicSharedMemorySize, SM_TOTAL);
    int grid = (B + 63) / 64;
    mlp_kernel<<<grid, 256, SM_TOTAL>>>(F, C, b2, b3, b4, b5, (float*)d_out, B);
}

// round 12
// speedup vs baseline: 2.2574x; 1.2422x over previous
#include <cuda_runtime.h>
#include <cuda_fp16.h>
#include <math.h>
#include <stdint.h>

#define EPSV 1e-6f

// ---- smem byte layout (172,544 B total; 1 CTA/SM) ----
#define SAH    0        // A hi: [64m][256k] fp16, 512B rows, byte^(16*(m&7))
#define SAL    32768    // A lo
#define SWRING 65536    // 6 slots x 16KB (chunk: hi 8KB + lo 8KB)
#define SBIAS  163840   // 4KB: b1eff, b2, b3, b4 (256 f32 each)
#define SD     167936   // L5 staging D[64][18] f32 (4608B)
#define SM_TOTAL 172544

// ---- device scratch: pre-split, pre-swizzled fp16 weight images ----
__device__ __align__(16) unsigned char g_W1img[32768];    // 2 chunks: [256n][16k] hi8K+lo8K
__device__ __align__(16) unsigned char g_W234img[786432]; // 48 chunks of 16KB (l*16+c)
__device__ __align__(16) unsigned char g_W5img[16384];    // [16n][256k] 512B rows, hi8K+lo8K
__device__ __align__(16) float g_latconst[256];

static __device__ __forceinline__ uint32_t smem_u32(const void* p){
    uint32_t a; asm("{ .reg .u64 t; cvta.to.shared.u64 t, %1; cvt.u32.u64 %0, t; }":"=r"(a):"l"(p)); return a;
}
static __device__ __forceinline__ void cp16(uint32_t d, const void* s){
    asm volatile("cp.async.cg.shared.global [%0], [%1], 16;"::"r"(d),"l"(s));
}
#define CP_COMMIT() asm volatile("cp.async.commit_group;":::"memory")
#define CP_WAIT0()  asm volatile("cp.async.wait_group 0;":::"memory")
#define CP_WAIT4()  asm volatile("cp.async.wait_group 4;":::"memory")

static __device__ __forceinline__ void mma16816(float* c, uint32_t a0, uint32_t a1, uint32_t a2, uint32_t a3,
                                                uint32_t b0, uint32_t b1){
    asm volatile("mma.sync.aligned.m16n8k16.row.col.f32.f16.f16.f32 "
                 "{%0,%1,%2,%3},{%4,%5,%6,%7},{%8,%9},{%0,%1,%2,%3};"
                 : "+f"(c[0]),"+f"(c[1]),"+f"(c[2]),"+f"(c[3])
                 : "r"(a0),"r"(a1),"r"(a2),"r"(a3),"r"(b0),"r"(b1));
}
static __device__ __forceinline__ float gelu_fast(float x){
    float z = fabsf(x)*0.70710678118654752f;
    float tt = __fdividef(1.0f, fmaf(0.3275911f, z, 1.0f));
    float poly = fmaf(fmaf(fmaf(fmaf(1.061405429f,tt,-1.453152027f),tt,1.421413741f),tt,-0.284496736f),tt,0.254829592f)*tt;
    float e = fmaf(-poly, __expf(-z*z), 1.0f);
    return 0.5f*x*(1.0f + copysignf(e, x));
}
static __device__ __forceinline__ void pack_split(float a, float b, uint32_t &ph, uint32_t &pl){
    __half ha = __float2half_rn(a), hb = __float2half_rn(b);
    __half la = __float2half_rn(a - __half2float(ha));
    __half lb = __float2half_rn(b - __half2float(hb));
    __half2 H = __halves2half2(ha,hb), L = __halves2half2(la,lb);
    ph = *(uint32_t*)&H; pl = *(uint32_t*)&L;
}

// ---------------- prep kernels ----------------
__global__ void latconst_kernel(const float* __restrict__ emb, const int* __restrict__ traj,
                                const float* __restrict__ W1, const float* __restrict__ b1){
    int n = threadIdx.x;
    const float* e = emb + (size_t)traj[0]*128;
    float s = b1[n];
#pragma unroll 4
    for (int j = 0; j < 128; ++j) s = fmaf(e[j], W1[(size_t)(25+j)*256+n], s);
    g_latconst[n] = s;
}

__global__ void prep_weights(const float* __restrict__ W1, const float* __restrict__ W2,
                             const float* __restrict__ W3, const float* __restrict__ W4,
                             const float* __restrict__ W5){
    int i = blockIdx.x*256 + threadIdx.x;            // 816 x 256 = 208896
    float v; unsigned char* dst; size_t off; int lo_delta;
    if (i < 196608) {                                // W2/3/4 -> k16 chunks, 32B rows
        int l = i / 65536, r = i % 65536, k = r >> 8, n = r & 255;
        const float* W = (l==0)?W2:(l==1)?W3:W4;
        v = W[(size_t)k*256+n];
        off = (size_t)(l*16 + (k>>4))*16384u + (size_t)n*32u
            + (size_t)(((uint32_t)(2*(k&15))) ^ (((uint32_t)n&4u)<<2));
        dst = g_W234img; lo_delta = 8192;
    } else if (i < 204800) {                         // W1: k<32 (pad>=25), 2 chunks
        int r = i-196608, n = r>>5, k = r&31;
        v = (k<25)? W1[(size_t)k*256+n] : 0.0f;
        off = (size_t)(k>>4)*16384u + (size_t)n*32u
            + (size_t)(((uint32_t)(2*(k&15))) ^ (((uint32_t)n&4u)<<2));
        dst = g_W1img; lo_delta = 8192;
    } else if (i < 208896) {                         // W5: [16n][256k] pad n>=9, 512B rows
        int r = i-204800, k = r>>4, n = r&15;
        v = (n<9)? W5[(size_t)k*9+n] : 0.0f;
        off = (size_t)n*512u + (size_t)(((uint32_t)(2*k)) ^ (((uint32_t)n&7u)<<4));
        dst = g_W5img; lo_delta = 8192;
    } else return;
    __half h = __float2half_rn(v);
    __half l = __float2half_rn(v - __half2float(h));
    *(__half*)(dst + off) = h;
    *(__half*)(dst + off + lo_delta) = l;
}

// ---------------- chunk streaming ----------------
static __device__ __forceinline__ void issue_u(uint32_t smb, int t, int u){
    if (u > 50) return;
    const unsigned char* s = (u < 2)  ? g_W1img + (size_t)u*16384
                           : (u < 50) ? g_W234img + (size_t)(u-2)*16384
                                      : g_W5img;
    uint32_t dst = smb + SWRING + (uint32_t)(u % 6)*16384u + (uint32_t)t*16u;
    const unsigned char* sp = s + (size_t)t*16;
#pragma unroll
    for (int i = 0; i < 4; ++i) cp16(dst + (uint32_t)i*4096u, sp + (size_t)i*4096);
}

// one k16 chunk of one layer: 3 products into acc[2][8]
static __device__ __forceinline__ void compute_chunk(const char* sm, int slot, int c,
        int wm, int wn, int g, int tig, float (&acc)[2][8][4]){
    const uint32_t gx = (uint32_t)g << 4;
    const uint32_t wx = ((uint32_t)g & 4u) << 2;
    const int kb = c*32 + 4*tig;
    const uint32_t k0A = (uint32_t)kb ^ gx, k1A = (uint32_t)(kb+16) ^ gx;
    const uint32_t k0W = ((uint32_t)(4*tig)) ^ wx, k1W = ((uint32_t)(4*tig+16)) ^ wx;
    uint32_t ah[2][4], al[2][4];
#pragma unroll
    for (int mt=0; mt<2; ++mt){
        const char* abh = sm + SAH + (wm*32 + g + mt*16)*512;
        const char* abl = abh + (SAL - SAH);
        ah[mt][0]=*(const uint32_t*)(abh+k0A); ah[mt][1]=*(const uint32_t*)(abh+4096+k0A);
        ah[mt][2]=*(const uint32_t*)(abh+k1A); ah[mt][3]=*(const uint32_t*)(abh+4096+k1A);
        al[mt][0]=*(const uint32_t*)(abl+k0A); al[mt][1]=*(const uint32_t*)(abl+4096+k0A);
        al[mt][2]=*(const uint32_t*)(abl+k1A); al[mt][3]=*(const uint32_t*)(abl+4096+k1A);
    }
    const char* wbase = sm + slot + (wn*64 + g)*32;
#pragma unroll
    for (int nt=0; nt<8; ++nt){
        const char* wbh = wbase + nt*256;
        const char* wbl = wbh + 8192;
        uint32_t bh0=*(const uint32_t*)(wbh+k0W), bh1=*(const uint32_t*)(wbh+k1W);
        uint32_t bl0=*(const uint32_t*)(wbl+k0W), bl1=*(const uint32_t*)(wbl+k1W);
#pragma unroll
        for (int mt=0; mt<2; ++mt){
            mma16816(acc[mt][nt], ah[mt][0],ah[mt][1],ah[mt][2],ah[mt][3], bh0,bh1);
            mma16816(acc[mt][nt], ah[mt][0],ah[mt][1],ah[mt][2],ah[mt][3], bl0,bl1);
            mma16816(acc[mt][nt], al[mt][0],al[mt][1],al[mt][2],al[mt][3], bh0,bh1);
        }
    }
}

static __device__ __forceinline__ void epilogue_layer(char* sm, int biasOff,
        int wm, int wn, int g, int tig, float (&acc)[2][8][4]){
#pragma unroll
    for (int mt=0; mt<2; ++mt){
        char* rbh = sm + SAH + (wm*32 + g + mt*16)*512;
        char* rbl = rbh + (SAL - SAH);
        const uint32_t gx = (uint32_t)g << 4;
#pragma unroll
        for (int nt=0; nt<8; ++nt){
            int n0 = wn*64 + nt*8 + 2*tig;
            float2 bb = *(const float2*)(sm + biasOff + n0*4);
            float* c = acc[mt][nt];
            float y0 = gelu_fast(c[0]+bb.x), y1 = gelu_fast(c[1]+bb.y);
            float y2 = gelu_fast(c[2]+bb.x), y3 = gelu_fast(c[3]+bb.y);
            uint32_t kb2 = ((uint32_t)(n0*2)) ^ gx;
            uint32_t ph0,pl0,ph1,pl1;
            pack_split(y0,y1,ph0,pl0); pack_split(y2,y3,ph1,pl1);
            *(uint32_t*)(rbh + kb2)        = ph0;
            *(uint32_t*)(rbh + 4096 + kb2) = ph1;
            *(uint32_t*)(rbl + kb2)        = pl0;
            *(uint32_t*)(rbl + 4096 + kb2) = pl1;
        }
    }
}

// ---------------- main kernel: 64 particles / CTA, 256 threads ----------------
__global__ void __launch_bounds__(256, 1)
mlp_kernel(const float* __restrict__ Fg, const float* __restrict__ Cg,
           const float* __restrict__ b2, const float* __restrict__ b3,
           const float* __restrict__ b4, const float* __restrict__ b5,
           float* __restrict__ outg, int B){
    extern __shared__ char sm[];
    const uint32_t smb = smem_u32(sm);
    const int t = threadIdx.x, w = t>>5, lane = t&31;
    const int g = lane>>2, tig = lane&3;
    const int wm = w>>2, wn = w&3;
    const int g0 = blockIdx.x*64;

    // ---- prologue: chunks 0..3 as 4 groups; biases with group 0 ----
    issue_u(smb, t, 0);
    {   // 4KB of biases: id = t>>6 (b1eff, b2, b3, b4), 16B each
        const char* src;
        switch (t >> 6){
            case 0:  src = (const char*)g_latconst; break;
            case 1:  src = (const char*)b2; break;
            case 2:  src = (const char*)b3; break;
            default: src = (const char*)b4; break;
        }
        cp16(smb + SBIAS + (uint32_t)t*16u, src + (size_t)(t & 63)*16);
    }
    CP_COMMIT();
    issue_u(smb, t, 1); CP_COMMIT();
    issue_u(smb, t, 2); CP_COMMIT();
    issue_u(smb, t, 3); CP_COMMIT();

    // ---- phase 1: features into A (k<32 window) + polar rotation in regs ----
    float R0=0,R1=0,R2=0,R3=0,R4=0,R5=0,R6=0,R7=0,R8=0;
    float F0=0,F1=0,F2=0,F3=0,F4=0,F5=0,F6=0,F7=0,F8=0;
    if (t < 64){
        int gp = g0 + t;
        float feat[25];
#pragma unroll
        for (int i=0;i<25;++i) feat[i]=0.0f;
        if (gp < B){
            const float* Fp = Fg + (size_t)gp*9;
            F0=Fp[0];F1=Fp[1];F2=Fp[2];F3=Fp[3];F4=Fp[4];F5=Fp[5];F6=Fp[6];F7=Fp[7];F8=Fp[8];
            float M00=F0*F0+F3*F3+F6*F6, M01=F0*F1+F3*F4+F6*F7, M02=F0*F2+F3*F5+F6*F8;
            float M11=F1*F1+F4*F4+F7*F7, M12=F1*F2+F4*F5+F7*F8, M22=F2*F2+F5*F5+F8*F8;
            float det = F0*(F4*F8-F5*F7) - F1*(F3*F8-F5*F6) + F2*(F3*F7-F4*F6);
            float q=(M00+M11+M22)*(1.0f/3.0f);
            float p1=M01*M01+M02*M02+M12*M12;
            float d0=M00-q,d1=M11-q,d2=M22-q;
            float p=sqrtf((d0*d0+d1*d1+d2*d2+2.0f*p1)*(1.0f/6.0f)+1e-30f);
            float ip=1.0f/p;
            float B00=d0*ip,B01=M01*ip,B02=M02*ip,B11=d1*ip,B12=M12*ip,B22=d2*ip;
            float detB=B00*(B11*B22-B12*B12)-B01*(B01*B22-B12*B02)+B02*(B01*B12-B11*B02);
            float rr=fminf(1.0f,fmaxf(-1.0f,0.5f*detB));
            float phi=acosf(rr)*(1.0f/3.0f);
            float e1=q+2.0f*p*cosf(phi);
            float e3=q+2.0f*p*cosf(phi+2.0943951023931953f);
            float e2=3.0f*q-e1-e3;
            float f00=fmaxf(F0,EPSV);
            feat[0]=sqrtf(fmaxf(e1,0.0f))-1.0f; feat[1]=sqrtf(fmaxf(e2,0.0f))-1.0f; feat[2]=sqrtf(fmaxf(e3,0.0f))-1.0f;
            feat[3]=M00-1.0f; feat[4]=M01; feat[5]=M02; feat[6]=M01; feat[7]=M11-1.0f; feat[8]=M12;
            feat[9]=M02; feat[10]=M12; feat[11]=M22-1.0f;
            feat[12]=det-1.0f; feat[13]=logf(det)-1.0f; feat[14]=f00-1.0f; feat[15]=logf(f00)-1.0f;
            const float* Cp = Cg + (size_t)gp*9;
#pragma unroll
            for (int i=0;i<9;++i) feat[16+i]=Cp[i];
            float X0=F0,X1=F1,X2=F2,X3=F3,X4=F4,X5=F5,X6=F6,X7=F7,X8=F8;
#pragma unroll
            for (int it=0; it<4; ++it){
                float C00=X4*X8-X5*X7, C01=-(X3*X8-X5*X6), C02=X3*X7-X4*X6;
                float C10=-(X1*X8-X2*X7), C11=X0*X8-X2*X6, C12=-(X0*X7-X1*X6);
                float C20=X1*X5-X2*X4, C21=-(X0*X5-X2*X3), C22=X0*X4-X1*X3;
                float h = 0.5f/(X0*C00+X1*C01+X2*C02);
                X0=0.5f*X0+C00*h; X1=0.5f*X1+C01*h; X2=0.5f*X2+C02*h;
                X3=0.5f*X3+C10*h; X4=0.5f*X4+C11*h; X5=0.5f*X5+C12*h;
                X6=0.5f*X6+C20*h; X7=0.5f*X7+C21*h; X8=0.5f*X8+C22*h;
            }
            R0=X0;R1=X1;R2=X2;R3=X3;R4=X4;R5=X5;R6=X6;R7=X7;R8=X8;
        }
        // write features hi/lo into A rows (logical bytes [0,64), swizzle 16*(m&7))
        uint32_t mx = ((uint32_t)t & 7u) << 4;
        char* frh = sm + SAH + t*512;
        char* frl = sm + SAL + t*512;
#pragma unroll
        for (int j=0;j<16;++j){
            float x0 = (2*j   < 25)? feat[2*j]   : 0.0f;
            float x1 = (2*j+1 < 25)? feat[2*j+1] : 0.0f;
            uint32_t ph,pl; pack_split(x0,x1,ph,pl);
            *(uint32_t*)(frh + (((uint32_t)(4*j)) ^ mx)) = ph;
            *(uint32_t*)(frl + (((uint32_t)(4*j)) ^ mx)) = pl;
        }
    }

    // ---- layers 1..4: unified 50-chunk stream, depth-4 pipeline ----
    int u = 0;
#pragma unroll 1
    for (int L = 0; L < 4; ++L){
        const int nc = (L == 0) ? 2 : 16;
        float acc[2][8][4];
#pragma unroll
        for (int mt=0;mt<2;++mt)
#pragma unroll
            for (int nt=0;nt<8;++nt)
#pragma unroll
                for (int j=0;j<4;++j) acc[mt][nt][j]=0.0f;
#pragma unroll 1
        for (int c = 0; c < nc; ++c, ++u){
            issue_u(smb, t, u+4);
            CP_COMMIT();
            CP_WAIT4();
            __syncthreads();
            compute_chunk(sm, SWRING + (u % 6)*16384, c, wm, wn, g, tig, acc);
        }
        __syncthreads();                       // all reads of A done
        epilogue_layer(sm, SBIAS + L*1024, wm, wn, g, tig, acc);
    }

    // ---- L5: chunk 50 (W5), computed by warps 0..3 ----
    CP_WAIT0();
    __syncthreads();
    {
        const int slot = SWRING + (50 % 6)*16384;
        if (w < 4){
            float acc5[2][4];
#pragma unroll
            for (int nt=0;nt<2;++nt)
#pragma unroll
                for (int j=0;j<4;++j) acc5[nt][j]=0.0f;
            int m0 = w*16 + g;
            const char* abh = sm + SAH + m0*512;
            const char* abl = sm + SAL + m0*512;
            uint32_t gx = (uint32_t)g<<4;
#pragma unroll
            for (int kc=0; kc<16; ++kc){
                int kb = kc*32 + 4*tig;
                uint32_t k0 = (uint32_t)kb ^ gx, k1 = (uint32_t)(kb+16) ^ gx;
                uint32_t ah0=*(const uint32_t*)(abh+k0), ah1=*(const uint32_t*)(abh+4096+k0);
                uint32_t ah2=*(const uint32_t*)(abh+k1), ah3=*(const uint32_t*)(abh+4096+k1);
                uint32_t al0=*(const uint32_t*)(abl+k0), al1=*(const uint32_t*)(abl+4096+k0);
                uint32_t al2=*(const uint32_t*)(abl+k1), al3=*(const uint32_t*)(abl+4096+k1);
#pragma unroll
                for (int nt=0; nt<2; ++nt){
                    const char* wbh = sm + slot + (nt*8+g)*512;
                    const char* wbl = wbh + 8192;
                    uint32_t bh0=*(const uint32_t*)(wbh+k0), bh1=*(const uint32_t*)(wbh+k1);
                    uint32_t bl0=*(const uint32_t*)(wbl+k0), bl1=*(const uint32_t*)(wbl+k1);
                    mma16816(acc5[nt], ah0,ah1,ah2,ah3, bh0,bh1);
                    mma16816(acc5[nt], ah0,ah1,ah2,ah3, bl0,bl1);
                    mma16816(acc5[nt], al0,al1,al2,al3, bh0,bh1);
                }
            }
#pragma unroll
            for (int nt=0; nt<2; ++nt){
                int n0 = nt*8 + 2*tig;
                *(float2*)(sm + SD + ((size_t)m0*18 + n0)*4)     = make_float2(acc5[nt][0], acc5[nt][1]);
                *(float2*)(sm + SD + ((size_t)(m0+8)*18 + n0)*4) = make_float2(acc5[nt][2], acc5[nt][3]);
            }
        }
    }
    __syncthreads();

    // ---- final epilogue: symmetrize, P = R x, cauchy = P F^T ----
    if (t < 64){
        int gp = g0 + t;
        if (gp < B){
            const float* dr = (const float*)(sm + SD + (size_t)t*72);
            float o[9];
#pragma unroll
            for (int j=0;j<9;++j) o[j] = dr[j] + b5[j];
            float x00=o[0], x11=o[4], x22=o[8];
            float x01=0.5f*(o[1]+o[3]), x02=0.5f*(o[2]+o[6]), x12=0.5f*(o[5]+o[7]);
            float P00=R0*x00+R1*x01+R2*x02, P01=R0*x01+R1*x11+R2*x12, P02=R0*x02+R1*x12+R2*x22;
            float P10=R3*x00+R4*x01+R5*x02, P11=R3*x01+R4*x11+R5*x12, P12=R3*x02+R4*x12+R5*x22;
            float P20=R6*x00+R7*x01+R8*x02, P21=R6*x01+R7*x11+R8*x12, P22=R6*x02+R7*x12+R8*x22;
            float* op = outg + (size_t)gp*9;
            op[0]=P00*F0+P01*F1+P02*F2; op[1]=P00*F3+P01*F4+P02*F5; op[2]=P00*F6+P01*F7+P02*F8;
            op[3]=P10*F0+P11*F1+P12*F2; op[4]=P10*F3+P11*F4+P12*F5; op[5]=P10*F6+P11*F7+P12*F8;
            op[6]=P20*F0+P21*F1+P22*F2; op[7]=P20*F3+P21*F4+P22*F5; op[8]=P20*F6+P21*F7+P22*F8;
        }
    }
}

// ---------------------------------------------------------------------------
extern "C" void kernel_launch(void* const* d_in, const int* in_sizes, int n_in,
                              void* d_out, int out_size){
    const float* F   = (const float*)d_in[0];
    const float* C   = (const float*)d_in[1];
    const float* emb = (const float*)d_in[2];
    const int* traj  = (const int*)d_in[3];
    const float* W1 = (const float*)d_in[4];  const float* b1 = (const float*)d_in[5];
    const float* W2 = (const float*)d_in[6];  const float* b2 = (const float*)d_in[7];
    const float* W3 = (const float*)d_in[8];  const float* b3 = (const float*)d_in[9];
    const float* W4 = (const float*)d_in[10]; const float* b4 = (const float*)d_in[11];
    const float* W5 = (const float*)d_in[12]; const float* b5 = (const float*)d_in[13];
    int B = in_sizes[0] / 9;

    latconst_kernel<<<1, 256>>>(emb, traj, W1, b1);
    prep_weights<<<816, 256>>>(W1, W2, W3, W4, W5);

    cudaFuncSetAttribute(mlp_kernel, cudaFuncAttributeMaxDynamicSharedMemorySize, SM_TOTAL);
    int grid = (B + 63) / 64;
    mlp_kernel<<<grid, 256, SM_TOTAL>>>(F, C, b2, b3, b4, b5, (float*)d_out, B);
}